// round 13
// baseline (speedup 1.0000x reference)
#include <cuda_runtime.h>
#include <math.h>

// WaveNet collapsed to the last-sample 32-dim recurrence (k=0 tap only),
// residual folded into the next layer's filter/gate at pack time:
//   A_L = -2 F_{L+1}(R_L+I), B_L = -G_{L+1}(R_L+I)
//   u_L = act(W_L u_{L-1});  skip += S_L u_L
//   out = end2 @ relu(end1 @ relu(skip) + b1) + b2
//
// R13: producer/consumer SPLIT ACROSS BLOCKS in one kernel (16 blocks):
//   blocks 0-7  (rec, batch b): warp0 folded recurrence from smem ring,
//       warps1-7 ring producers. Publishes u per 4-layer chunk to global
//       + epoch-stamped flag. Block 0 also does the final reduce.
//   blocks 8-15 (skip, ch-group cg): 32 channels x ALL 8 batches. Stages
//       its 16KB/chunk S slice to smem (transpose from original skip_w),
//       waits flags, smem GEMV one chunk behind; then end1 partials.
//   Cross-block sync: per-launch epoch = atomicAdd(g_epoch)/16; flags are
//   monotone (store epoch+1) => safe across CUDA-graph replays.
//  Pack kernel: only the per-layer fold matmul + start conv (41 blocks).

#define NL   40
#define RC   32
#define SC   256
#define CIN  6
#define T_IN 8192
#define FULLM 0xffffffffu

#define CH   4                 // layers per chunk
#define NCH  (NL / CH)         // 10
#define LW   512               // float4 per layer (A@0, B@256)
#define CW   (CH * LW)         // float4 per chunk = 2048

// skip-block smem carve (floats)
#define SSTR    33                     // padded S row stride (bank-spread)
#define S_CHF   (128 * SSTR)           // 4224 floats per S chunk buffer
#define OFF_S   0                      // S_sm[2][S_CHF]
#define OFF_U   (2 * S_CHF)            // u_sm[8][128]
#define OFF_HS  (OFF_U + 8 * 128)      // hs_sm[8][32]
#define OFF_E1  (OFF_HS + 256)         // E1_sm[32][257]
#define ESTR    257
#define SMEM_FLOATS (OFF_E1 + 32 * ESTR)   // 17952 floats = 71808 B
#define SMEM_BYTES  73728

typedef unsigned long long u64;

__device__ float    g_pk[NL * 2048];     // folded A/B, 328 KB
__device__ float    g_xs0[8 * RC];
__device__ float    g_us[8 * NL * RC];   // u activations
__device__ float    g_e1p[8 * 8 * SC];   // end1 partials [cg][b][co]
__device__ unsigned g_uflag[8 * NCH];    // [b][q]
__device__ unsigned g_pflag[8];          // [cg]
__device__ unsigned g_epoch;

__device__ __forceinline__ void fma2(u64& d, u64 a, u64 b) {
    asm("fma.rn.f32x2 %0, %1, %2, %3;" : "=l"(d) : "l"(a), "l"(b), "l"(d));
}
__device__ __forceinline__ void add2(u64& d, u64 a, u64 b) {
    asm("add.rn.f32x2 %0, %1, %2;" : "=l"(d) : "l"(a), "l"(b));
}
__device__ __forceinline__ float2 upk(u64 v) {
    float2 r; asm("mov.b64 {%0, %1}, %2;" : "=f"(r.x), "=f"(r.y) : "l"(v));
    return r;
}

// ---------------------------------------------------------------- pack
// blocks 0..39: per-layer fold matmul; block 40: start conv.
__global__ __launch_bounds__(256, 1)
void wn_pack(const float* __restrict__ x,
             const float* __restrict__ start_w,
             const float* __restrict__ filter_w,
             const float* __restrict__ gate_w,
             const float* __restrict__ res_w)
{
    const int blk = blockIdx.x;
    const int tid = threadIdx.x;

    if (blk < NL) {
        const int L = blk;
        __shared__ float Fk[RC][RC];   // -2 * filter k0 taps
        __shared__ float Gk[RC][RC];   // -1 * gate   k0 taps
        __shared__ float Rp[RC][RC];   // R_{L-1} + I

        #pragma unroll
        for (int s = 0; s < 2; s++) {
            const int d  = tid + 256 * s;
            const int i  = d >> 4;
            const int rm = d & 15;
            const float4 fv = *(const float4*)(filter_w + L * 2048 + 4 * d);
            const float4 gv = *(const float4*)(gate_w   + L * 2048 + 4 * d);
            Fk[i][2 * rm]     = -2.f * fv.x;
            Fk[i][2 * rm + 1] = -2.f * fv.z;
            Gk[i][2 * rm]     = -gv.x;
            Gk[i][2 * rm + 1] = -gv.z;
        }
        if (L > 0) {
            const int k  = tid >> 3;
            const int j0 = (tid & 7) * 4;
            float4 r4 = *(const float4*)(res_w + (L - 1) * 1024 + k * RC + j0);
            if (k >= j0 && k < j0 + 4) (&r4.x)[k - j0] += 1.f;
            *(float4*)&Rp[k][j0] = r4;
        }
        __syncthreads();

        const int jg = tid >> 5;
        const int i  = tid & 31;
        float4 accA, accB;
        if (L == 0) {
            accA = *(const float4*)&Fk[i][4 * jg];
            accB = *(const float4*)&Gk[i][4 * jg];
        } else {
            accA = make_float4(0.f, 0.f, 0.f, 0.f);
            accB = make_float4(0.f, 0.f, 0.f, 0.f);
            #pragma unroll
            for (int k = 0; k < RC; k++) {
                const float4 r4 = *(const float4*)&Rp[k][4 * jg];
                const float fv = Fk[i][k];
                const float gv = Gk[i][k];
                accA.x = fmaf(fv, r4.x, accA.x); accA.y = fmaf(fv, r4.y, accA.y);
                accA.z = fmaf(fv, r4.z, accA.z); accA.w = fmaf(fv, r4.w, accA.w);
                accB.x = fmaf(gv, r4.x, accB.x); accB.y = fmaf(gv, r4.y, accB.y);
                accB.z = fmaf(gv, r4.z, accB.z); accB.w = fmaf(gv, r4.w, accB.w);
            }
        }
        ((float4*)g_pk)[L * LW + jg * 32 + i]       = accA;
        ((float4*)g_pk)[L * LW + 256 + jg * 32 + i] = accB;
    } else {
        // start conv: 256 items, 1/thread
        const int b = tid >> 5, i = tid & 31;
        float s = 0.f;
        #pragma unroll
        for (int ci = 0; ci < CIN; ci++)
            s += start_w[i * CIN + ci] * x[(b * CIN + ci) * T_IN + (T_IN - 1)];
        g_xs0[b * RC + i] = s;
    }
}

// ---------------------------------------------------------------- main
extern __shared__ float sm[];

__global__ __launch_bounds__(256, 1)
void wn_main(const float* __restrict__ skip_w,
             const float* __restrict__ end1_w,
             const float* __restrict__ end1_b,
             const float* __restrict__ end2_w,
             const float* __restrict__ end2_b,
             float* __restrict__ out)
{
    const int blk  = blockIdx.x;
    const int tid  = threadIdx.x;
    const int lane = tid & 31;
    const int warp = tid >> 5;

    __shared__ unsigned s_tgt;
    if (tid == 0) s_tgt = atomicAdd(&g_epoch, 1u) / 16u + 1u;
    __syncthreads();
    const unsigned tgt = s_tgt;

    if (blk < 8) {
        // ================= recurrence block (batch b) =================
        const int b = blk;
        float4* ring = (float4*)sm;          // [2][CW]
        __shared__ __align__(16) float vbuf[2][RC];

        // prologue: stage chunk 0 (8 f4/thread exact)
        {
            const float4* src = (const float4*)g_pk;
            float4 t[8];
            #pragma unroll
            for (int k = 0; k < 8; k++) t[k] = src[tid + 256 * k];
            #pragma unroll
            for (int k = 0; k < 8; k++) ring[tid + 256 * k] = t[k];
        }
        if (warp == 0) vbuf[0][lane] = g_xs0[b * RC + lane];
        __syncthreads();

        for (int q = 0; q <= NCH; q++) {
            if (warp == 0) {
                if (q < NCH) {
                    const float4* wc = ring + (q & 1) * CW;
                    #pragma unroll
                    for (int l = 0; l < CH; l++) {
                        const int L   = q * CH + l;
                        const int par = l & 1;
                        const float4* wl = wc + l * LW + lane;

                        u64 fa = 0ull, fb = 0ull, ga = 0ull, gb = 0ull;
                        #pragma unroll
                        for (int jg = 0; jg < 8; jg++) {
                            const ulonglong2 vv = *(const ulonglong2*)&vbuf[par][4 * jg];
                            const ulonglong2 Aw = *(const ulonglong2*)(wl + jg * 32);
                            const ulonglong2 Bw = *(const ulonglong2*)(wl + 256 + jg * 32);
                            fma2(fa, Aw.x, vv.x); fma2(fb, Aw.y, vv.y);
                            fma2(ga, Bw.x, vv.x); fma2(gb, Bw.y, vv.y);
                        }
                        add2(fa, fa, fb);
                        add2(ga, ga, gb);
                        const float2 fp = upk(fa);
                        const float2 gp = upk(ga);
                        const float e1 = __expf(fp.x + fp.y);   // e^{-2f}
                        const float e2 = __expf(gp.x + gp.y);   // e^{-g}
                        const float u  = __fdividef(1.f - e1, (1.f + e1) * (1.f + e2));
                        g_us[b * (NL * RC) + L * RC + lane] = u;
                        vbuf[par ^ 1][lane] = u;
                        __syncwarp();
                    }
                    // publish chunk q
                    __threadfence();
                    __syncwarp();
                    if (lane == 0) atomicExch(&g_uflag[b * NCH + q], tgt);
                }
            } else {
                if (q + 1 < NCH) {
                    const float4* src = (const float4*)g_pk + (q + 1) * CW;
                    float4*       dst = ring + ((q + 1) & 1) * CW;
                    const int t0 = tid - 32;           // 0..223
                    float4 t[10];
                    #pragma unroll
                    for (int k = 0; k < 10; k++) {
                        const int i = t0 + 224 * k;
                        if (i < CW) t[k] = src[i];
                    }
                    #pragma unroll
                    for (int k = 0; k < 10; k++) {
                        const int i = t0 + 224 * k;
                        if (i < CW) dst[i] = t[k];
                    }
                }
            }
            __syncthreads();
        }

        // ---- final reduce (block 0 only): wait end1 partials, finish head
        if (blk == 0) {
            const int b2  = warp;
            const int co8 = lane;
            #pragma unroll
            for (int cg = 0; cg < 8; cg++)
                while (((volatile unsigned*)g_pflag)[cg] < tgt) { }
            __threadfence();
            float o = 0.f;
            #pragma unroll
            for (int m = 0; m < 8; m++) {
                const int co = co8 + 32 * m;
                float e = end1_b[co];
                #pragma unroll
                for (int cg = 0; cg < 8; cg++)
                    e += g_e1p[(cg * 8 + b2) * SC + co];
                o = fmaf(end2_w[co], fmaxf(e, 0.f), o);
            }
            #pragma unroll
            for (int off = 16; off > 0; off >>= 1)
                o += __shfl_xor_sync(FULLM, o, off);
            if (lane == 0) out[b2] = o + end2_b[0];
        }
    } else {
        // ================= skip block (channel group cg) =================
        const int cg = blk - 8;
        float* S_sm  = sm + OFF_S;     // [2][128][SSTR]
        float* u_sm  = sm + OFF_U;     // [8][128]
        float* hs_sm = sm + OFF_HS;    // [8][32]
        float* E1_sm = sm + OFF_E1;    // [32][ESTR]
        const int b = warp;            // warp = batch

        // stage E1 slice (transpose end1_w[co][ci] -> E1_sm[cl][co])
        #pragma unroll
        for (int s = 0; s < 8; s++) {
            const int id  = tid + 256 * s;
            const int co  = id >> 3;
            const int ci4 = id & 7;
            const float4 v = *(const float4*)(end1_w + co * SC + cg * 32 + 4 * ci4);
            E1_sm[(4 * ci4 + 0) * ESTR + co] = v.x;
            E1_sm[(4 * ci4 + 1) * ESTR + co] = v.y;
            E1_sm[(4 * ci4 + 2) * ESTR + co] = v.z;
            E1_sm[(4 * ci4 + 3) * ESTR + co] = v.w;
        }
        // stage S chunk 0 (transpose skip_w[L][c][j] -> S_sm[k][cl])
        {
            float* dst = S_sm;
            #pragma unroll
            for (int s = 0; s < 4; s++) {
                const int id  = tid + 256 * s;
                const int Ll  = id >> 8;
                const int cl  = (id >> 3) & 31;
                const int j4  = id & 7;
                const float4 v = *(const float4*)(skip_w + Ll * (SC * RC)
                                                  + (cg * 32 + cl) * RC + 4 * j4);
                const int k0 = Ll * 32 + 4 * j4;
                dst[(k0 + 0) * SSTR + cl] = v.x;
                dst[(k0 + 1) * SSTR + cl] = v.y;
                dst[(k0 + 2) * SSTR + cl] = v.z;
                dst[(k0 + 3) * SSTR + cl] = v.w;
            }
        }
        __syncthreads();

        float acc = 0.f;
        for (int q = 0; q < NCH; q++) {
            // stage next S chunk (independent of flags)
            if (q + 1 < NCH) {
                float* dst = S_sm + ((q + 1) & 1) * S_CHF;
                #pragma unroll
                for (int s = 0; s < 4; s++) {
                    const int id  = tid + 256 * s;
                    const int Ll  = id >> 8;
                    const int cl  = (id >> 3) & 31;
                    const int j4  = id & 7;
                    const float4 v = *(const float4*)(skip_w
                        + ((q + 1) * CH + Ll) * (SC * RC)
                        + (cg * 32 + cl) * RC + 4 * j4);
                    const int k0 = Ll * 32 + 4 * j4;
                    dst[(k0 + 0) * SSTR + cl] = v.x;
                    dst[(k0 + 1) * SSTR + cl] = v.y;
                    dst[(k0 + 2) * SSTR + cl] = v.z;
                    dst[(k0 + 3) * SSTR + cl] = v.w;
                }
            }
            // wait for this batch's u chunk
            while (((volatile unsigned*)g_uflag)[b * NCH + q] < tgt) { }
            __threadfence();
            // stage u (1 f4 per lane: 128 floats)
            {
                const float4 uv = *(const float4*)(g_us + b * (NL * RC)
                                                   + q * (CH * RC) + 4 * lane);
                *(float4*)&u_sm[b * 128 + 4 * lane] = uv;
            }
            __syncwarp();
            // GEMV: acc += sum_k S[k][lane] * u[b][k]
            const float* Sb = S_sm + (q & 1) * S_CHF;
            #pragma unroll
            for (int kg = 0; kg < 32; kg++) {
                const float4 u4 = *(const float4*)&u_sm[b * 128 + 4 * kg];
                acc = fmaf(Sb[(4 * kg + 0) * SSTR + lane], u4.x,
                      fmaf(Sb[(4 * kg + 1) * SSTR + lane], u4.y,
                      fmaf(Sb[(4 * kg + 2) * SSTR + lane], u4.z,
                      fmaf(Sb[(4 * kg + 3) * SSTR + lane], u4.w, acc))));
            }
            __syncthreads();
        }

        hs_sm[b * 32 + lane] = fmaxf(acc, 0.f);
        __syncthreads();

        // end1 partials: p[cg][b][co] = sum_{cl} E1[co][32cg+cl] * hs[b][cl]
        {
            const int co8 = lane;
            float pacc[8];
            #pragma unroll
            for (int m = 0; m < 8; m++) pacc[m] = 0.f;
            #pragma unroll
            for (int cl = 0; cl < 32; cl++) {
                const float h = hs_sm[b * 32 + cl];
                #pragma unroll
                for (int m = 0; m < 8; m++)
                    pacc[m] = fmaf(E1_sm[cl * ESTR + co8 + 32 * m], h, pacc[m]);
            }
            #pragma unroll
            for (int m = 0; m < 8; m++)
                g_e1p[(cg * 8 + b) * SC + co8 + 32 * m] = pacc[m];
        }
        __threadfence();
        __syncthreads();
        if (tid == 0) atomicExch(&g_pflag[cg], tgt);
    }
}

extern "C" void kernel_launch(void* const* d_in, const int* in_sizes, int n_in,
                              void* d_out, int out_size)
{
    const float* x        = (const float*)d_in[0];
    const float* start_w  = (const float*)d_in[1];
    const float* filter_w = (const float*)d_in[2];
    const float* gate_w   = (const float*)d_in[3];
    const float* res_w    = (const float*)d_in[4];
    const float* skip_w   = (const float*)d_in[5];
    const float* end1_w   = (const float*)d_in[6];
    const float* end1_b   = (const float*)d_in[7];
    const float* end2_w   = (const float*)d_in[8];
    const float* end2_b   = (const float*)d_in[9];
    float* out = (float*)d_out;

    cudaFuncSetAttribute(wn_main,
                         cudaFuncAttributeMaxDynamicSharedMemorySize,
                         SMEM_BYTES);

    wn_pack<<<41, 256>>>(x, start_w, filter_w, gate_w, res_w);
    wn_main<<<16, 256, SMEM_BYTES>>>(skip_w, end1_w, end1_b, end2_w, end2_b,
                                     out);
}

// round 14
// speedup vs baseline: 1.3117x; 1.3117x over previous
#include <cuda_runtime.h>
#include <cuda_fp16.h>
#include <math.h>

// WaveNet collapsed to the last-sample 32-dim recurrence (k=0 tap only),
// residual folded into the next layer's filter/gate at pack time, with
// log2(e) baked so activations use raw ex2:
//   A_L = -2*log2e*F_{L+1}(R_L+I), B_L = -log2e*G_{L+1}(R_L+I)
//   e1 = 2^(A u), e2 = 2^(B u);  u = (1-e1)/((1+e1)(1+e2))
//   skip += S_L u;  out = end2 @ relu(end1 @ relu(skip) + b1) + b2
//
// R14 = R7/R11 two-kernel shape + R12 fold + fp16 skip/end1 + CH=8.
//  1) wn_pack : blocks 0..39 fold matmul; rest: fp16 skipT/end1T + start.
//  2) wn_main : grid=8 (batch), 256 thr, 128KB smem weight ring.
//     warp 0    : folded recurrence from SMEM (LDS.128 + f32x2 FMAs).
//     warps 1-7 : batched ring producers + fp16 skip GEMM one chunk behind;
//                 then the fp16 end1/end2 head.

#define NL   40
#define RC   32
#define SC   256
#define CIN  6
#define T_IN 8192
#define FULLM 0xffffffffu

#define CH   8                 // layers per chunk
#define NCH  (NL / CH)         // 5
#define LW   512               // float4 per layer (A@0, B@256)
#define CW   (CH * LW)         // float4 per chunk = 4096
#define RING_BYTES (2 * CW * 16)   // 131072

typedef unsigned long long u64;

__device__ float  g_pk[NL * 2048];           // folded A/B, fp32, 328 KB
__device__ __half g_skipH[(NL * RC) * SC];   // [kg8][c][8kk] fp16, 655 KB
__device__ __half g_end1H[SC * SC];          // [jg8][c][8jj] fp16, 128 KB
__device__ float  g_xs0[8 * RC];

__device__ __forceinline__ void fma2(u64& d, u64 a, u64 b) {
    asm("fma.rn.f32x2 %0, %1, %2, %3;" : "=l"(d) : "l"(a), "l"(b), "l"(d));
}
__device__ __forceinline__ void add2(u64& d, u64 a, u64 b) {
    asm("add.rn.f32x2 %0, %1, %2;" : "=l"(d) : "l"(a), "l"(b));
}
__device__ __forceinline__ float2 upk(u64 v) {
    float2 r; asm("mov.b64 {%0, %1}, %2;" : "=f"(r.x), "=f"(r.y) : "l"(v));
    return r;
}
__device__ __forceinline__ float ex2(float v) {
    float r; asm("ex2.approx.f32 %0, %1;" : "=f"(r) : "f"(v));
    return r;
}
__device__ __forceinline__ unsigned h2u(__half2 h) {
    unsigned u; *reinterpret_cast<__half2*>(&u) = h; return u;
}
__device__ __forceinline__ __half2 u2h(unsigned u) {
    return *reinterpret_cast<__half2*>(&u);
}
__device__ __forceinline__ uint4 pack8h(float4 a, float4 c) {
    uint4 o;
    o.x = h2u(__floats2half2_rn(a.x, a.y));
    o.y = h2u(__floats2half2_rn(a.z, a.w));
    o.z = h2u(__floats2half2_rn(c.x, c.y));
    o.w = h2u(__floats2half2_rn(c.z, c.w));
    return o;
}
__device__ __forceinline__ float dot8h(uint4 s8, const float* u) {
    const float2 p0 = __half22float2(u2h(s8.x));
    const float2 p1 = __half22float2(u2h(s8.y));
    const float2 p2 = __half22float2(u2h(s8.z));
    const float2 p3 = __half22float2(u2h(s8.w));
    float a = fmaf(p0.x, u[0], 0.f);
    a = fmaf(p0.y, u[1], a);
    a = fmaf(p1.x, u[2], a);
    a = fmaf(p1.y, u[3], a);
    a = fmaf(p2.x, u[4], a);
    a = fmaf(p2.y, u[5], a);
    a = fmaf(p3.x, u[6], a);
    a = fmaf(p3.y, u[7], a);
    return a;
}

// ---------------------------------------------------------------- pack
// blocks 0..39: fold matmul; blocks 40+: fp16 skipT/end1T copies + start.
__global__ __launch_bounds__(256, 1)
void wn_pack(const float* __restrict__ x,
             const float* __restrict__ start_w,
             const float* __restrict__ filter_w,
             const float* __restrict__ gate_w,
             const float* __restrict__ res_w,
             const float* __restrict__ skip_w,
             const float* __restrict__ end1_w)
{
    const int blk = blockIdx.x;
    const int tid = threadIdx.x;

    if (blk < NL) {
        // ---- per-layer fold: slot L uses F/G of layer L, R of layer L-1
        const int L = blk;
        const float LOG2E = 1.4426950408889634f;
        __shared__ float Fk[RC][RC];   // -2*log2e * filter k0 taps
        __shared__ float Gk[RC][RC];   // -log2e   * gate   k0 taps
        __shared__ float Rp[RC][RC];   // R_{L-1} + I

        #pragma unroll
        for (int s = 0; s < 2; s++) {
            const int d  = tid + 256 * s;
            const int i  = d >> 4;
            const int rm = d & 15;
            const float4 fv = *(const float4*)(filter_w + L * 2048 + 4 * d);
            const float4 gv = *(const float4*)(gate_w   + L * 2048 + 4 * d);
            Fk[i][2 * rm]     = -2.f * LOG2E * fv.x;
            Fk[i][2 * rm + 1] = -2.f * LOG2E * fv.z;
            Gk[i][2 * rm]     = -LOG2E * gv.x;
            Gk[i][2 * rm + 1] = -LOG2E * gv.z;
        }
        if (L > 0) {
            const int k  = tid >> 3;
            const int j0 = (tid & 7) * 4;
            float4 r4 = *(const float4*)(res_w + (L - 1) * 1024 + k * RC + j0);
            if (k >= j0 && k < j0 + 4) (&r4.x)[k - j0] += 1.f;
            *(float4*)&Rp[k][j0] = r4;
        }
        __syncthreads();

        const int jg = tid >> 5;
        const int i  = tid & 31;
        float4 accA, accB;
        if (L == 0) {
            accA = *(const float4*)&Fk[i][4 * jg];
            accB = *(const float4*)&Gk[i][4 * jg];
        } else {
            accA = make_float4(0.f, 0.f, 0.f, 0.f);
            accB = make_float4(0.f, 0.f, 0.f, 0.f);
            #pragma unroll
            for (int k = 0; k < RC; k++) {
                const float4 r4 = *(const float4*)&Rp[k][4 * jg];
                const float fv = Fk[i][k];
                const float gv = Gk[i][k];
                accA.x = fmaf(fv, r4.x, accA.x); accA.y = fmaf(fv, r4.y, accA.y);
                accA.z = fmaf(fv, r4.z, accA.z); accA.w = fmaf(fv, r4.w, accA.w);
                accB.x = fmaf(gv, r4.x, accB.x); accB.y = fmaf(gv, r4.y, accB.y);
                accB.z = fmaf(gv, r4.z, accB.z); accB.w = fmaf(gv, r4.w, accB.w);
            }
        }
        ((float4*)g_pk)[L * LW + jg * 32 + i]       = accA;
        ((float4*)g_pk)[L * LW + 256 + jg * 32 + i] = accB;
    } else {
        // ---- copies: skipH (40960 u4), end1H (8192 u4), xs0 (256)
        const int NB = NL * RC * SC / 8;   // 40960
        const int NC = SC * SC / 8;        // 8192
        const int total = NB + NC + 8 * RC;
        const int nthr = 128 * 256;
        for (int idx = (blk - NL) * 256 + tid; idx < total; idx += nthr) {
            if (idx < NB) {
                const int kg8 = idx >> 8;
                const int c   = idx & 255;
                const int k0  = kg8 * 8;
                const int L   = k0 >> 5;
                const int j0  = k0 & 31;
                const float* src = skip_w + L * (SC * RC) + c * RC + j0;
                ((uint4*)g_skipH)[idx] =
                    pack8h(*(const float4*)src, *(const float4*)(src + 4));
            } else if (idx < NB + NC) {
                const int t   = idx - NB;
                const int jg8 = t >> 8;
                const int c   = t & 255;
                const float* src = end1_w + c * SC + jg8 * 8;
                ((uint4*)g_end1H)[t] =
                    pack8h(*(const float4*)src, *(const float4*)(src + 4));
            } else {
                const int t = idx - NB - NC;
                const int b = t / RC, i = t % RC;
                float s = 0.f;
                #pragma unroll
                for (int ci = 0; ci < CIN; ci++)
                    s += start_w[i * CIN + ci] * x[(b * CIN + ci) * T_IN + (T_IN - 1)];
                g_xs0[b * RC + i] = s;
            }
        }
    }
}

// ---------------------------------------------------------------- main
extern __shared__ float ring[];    // RING_BYTES dynamic smem

__global__ __launch_bounds__(256, 1)
void wn_main(const float* __restrict__ end1_b,
             const float* __restrict__ end2_w,
             const float* __restrict__ end2_b,
             float* __restrict__ out)
{
    const int b    = blockIdx.x;
    const int tid  = threadIdx.x;
    const int lane = tid & 31;
    const int warp = tid >> 5;

    __shared__ __align__(16) float us_all[NL * RC];   // 5.1 KB
    __shared__ __align__(16) float vbuf[2][RC];       // ping-pong state
    __shared__ __align__(16) float hs[SC];
    __shared__ float red8[8];

    // skip-thread channel mapping: warps 1-7 -> c0 in [0,224);
    // warp 1 additionally owns c1 in [224,256).
    const int  c0   = tid - 32;
    const bool dual = (warp == 1);
    const int  c1   = tid + 192;
    float acc0 = 0.f, acc1 = 0.f;

    // prologue: copy chunk 0 (16 float4 each, exact)
    {
        const float4* src = (const float4*)g_pk;
        float4*       dst = (float4*)ring;
        float4 t[16];
        #pragma unroll
        for (int k = 0; k < 16; k++) t[k] = src[tid + 256 * k];
        #pragma unroll
        for (int k = 0; k < 16; k++) dst[tid + 256 * k] = t[k];
    }
    if (warp == 0) vbuf[0][lane] = g_xs0[b * RC + lane];
    __syncthreads();

    for (int q = 0; q <= NCH; q++) {
        if (warp == 0) {
            if (q < NCH) {
                const float4* wc = (const float4*)ring + (q & 1) * CW;
                #pragma unroll
                for (int l = 0; l < CH; l++) {
                    const int L   = q * CH + l;
                    const int par = l & 1;          // CH even => par == L&1
                    const float4* wl = wc + l * LW + lane;

                    u64 fa = 0ull, fb = 0ull, ga = 0ull, gb = 0ull;
                    #pragma unroll
                    for (int jg = 0; jg < 8; jg++) {
                        const ulonglong2 vv = *(const ulonglong2*)&vbuf[par][4 * jg];
                        const ulonglong2 Aw = *(const ulonglong2*)(wl + jg * 32);
                        const ulonglong2 Bw = *(const ulonglong2*)(wl + 256 + jg * 32);
                        fma2(fa, Aw.x, vv.x); fma2(fb, Aw.y, vv.y);
                        fma2(ga, Bw.x, vv.x); fma2(gb, Bw.y, vv.y);
                    }
                    add2(fa, fa, fb);
                    add2(ga, ga, gb);
                    const float2 fp = upk(fa);
                    const float2 gp = upk(ga);
                    const float e1 = ex2(fp.x + fp.y);   // e^{-2f}
                    const float e2 = ex2(gp.x + gp.y);   // e^{-g}
                    // u = tanh(f)*sig(g) = (1-e1)/((1+e1)(1+e2))
                    const float u = __fdividef(1.f - e1, (1.f + e1) * (1.f + e2));
                    us_all[L * RC + lane] = u;
                    vbuf[par ^ 1][lane] = u;
                    __syncwarp();
                }
            }
        } else {
            // producers: batched stage of chunk q+1 into the other ring slot
            if (q + 1 < NCH) {
                const float4* src = (const float4*)g_pk + (q + 1) * CW;
                float4*       dst = (float4*)ring + ((q + 1) & 1) * CW;
                const int t0 = tid - 32;           // 0..223
                float4 t[19];
                #pragma unroll
                for (int k = 0; k < 19; k++) {
                    const int i = t0 + 224 * k;
                    if (i < CW) t[k] = src[i];
                }
                #pragma unroll
                for (int k = 0; k < 19; k++) {
                    const int i = t0 + 224 * k;
                    if (i < CW) dst[i] = t[k];
                }
            }
            // fp16 skip GEMM for chunk q-1: 32 k-groups of 8
            if (q >= 1) {
                const int cq = q - 1;
                const uint4* sp = (const uint4*)g_skipH + (32 * cq) * 256;
                const float* up = us_all + cq * (CH * RC);
                #pragma unroll
                for (int kg8 = 0; kg8 < 32; kg8++) {
                    acc0 += dot8h(sp[kg8 * 256 + c0], up + 8 * kg8);
                    if (dual)
                        acc1 += dot8h(sp[kg8 * 256 + c1], up + 8 * kg8);
                }
            }
        }
        __syncthreads();
    }

    // ---- head (fp16 end1)
    if (warp > 0) {
        hs[c0] = fmaxf(acc0, 0.f);
        if (dual) hs[c1] = fmaxf(acc1, 0.f);
    }
    __syncthreads();

    float o = 0.f;
    if (warp > 0) {
        float e0 = end1_b[c0];
        float e1v = dual ? end1_b[c1] : 0.f;
        const uint4* ep = (const uint4*)g_end1H;
        #pragma unroll
        for (int jg8 = 0; jg8 < 32; jg8++) {
            e0 += dot8h(ep[jg8 * 256 + c0], hs + 8 * jg8);
            if (dual)
                e1v += dot8h(ep[jg8 * 256 + c1], hs + 8 * jg8);
        }
        o = end2_w[c0] * fmaxf(e0, 0.f);
        if (dual) o += end2_w[c1] * fmaxf(e1v, 0.f);
    }
    #pragma unroll
    for (int off = 16; off > 0; off >>= 1)
        o += __shfl_xor_sync(FULLM, o, off);
    if (lane == 0) red8[warp] = o;
    __syncthreads();
    if (tid == 0) {
        float tot = 0.f;
        #pragma unroll
        for (int w = 0; w < 8; w++) tot += red8[w];
        out[b] = tot + end2_b[0];
    }
}

extern "C" void kernel_launch(void* const* d_in, const int* in_sizes, int n_in,
                              void* d_out, int out_size)
{
    const float* x        = (const float*)d_in[0];
    const float* start_w  = (const float*)d_in[1];
    const float* filter_w = (const float*)d_in[2];
    const float* gate_w   = (const float*)d_in[3];
    const float* res_w    = (const float*)d_in[4];
    const float* skip_w   = (const float*)d_in[5];
    const float* end1_w   = (const float*)d_in[6];
    const float* end1_b   = (const float*)d_in[7];
    const float* end2_w   = (const float*)d_in[8];
    const float* end2_b   = (const float*)d_in[9];
    float* out = (float*)d_out;

    cudaFuncSetAttribute(wn_main,
                         cudaFuncAttributeMaxDynamicSharedMemorySize,
                         RING_BYTES);

    wn_pack<<<168, 256>>>(x, start_w, filter_w, gate_w, res_w, skip_w, end1_w);
    wn_main<<<8, 256, RING_BYTES>>>(end1_b, end2_w, end2_b, out);
}

// round 15
// speedup vs baseline: 1.4046x; 1.0708x over previous
#include <cuda_runtime.h>
#include <cuda_fp16.h>
#include <math.h>

// WaveNet collapsed to the last-sample 32-dim recurrence (k=0 tap only),
// residual folded into the next layer's filter/gate at pack time, log2e
// baked so activations are raw ex2:
//   A_L = -2*log2e*F_{L+1}(R_L+I), B_L = -log2e*G_{L+1}(R_L+I)
//   e1 = 2^(A u), e2 = 2^(B u);  u = (1-e1)/((1+e1)(1+e2))
//   skip += S_L u;  out = end2 @ relu(end1 @ relu(skip) + b1) + b2
//
// R15 = R14 + balanced skip warps: block=288 (9 warps); warp 0 recurrence,
// warps 1-8 = 256 skip channels (exactly 1/thread, no dual straggler),
// producers spread over all 256 skip threads (16 f4 each, exact).

#define NL   40
#define RC   32
#define SC   256
#define CIN  6
#define T_IN 8192
#define FULLM 0xffffffffu

#define CH   8                 // layers per chunk
#define NCH  (NL / CH)         // 5
#define LW   512               // float4 per layer (A@0, B@256)
#define CW   (CH * LW)         // float4 per chunk = 4096
#define RING_BYTES (2 * CW * 16)   // 131072

typedef unsigned long long u64;

__device__ float  g_pk[NL * 2048];           // folded A/B, fp32, 328 KB
__device__ __half g_skipH[(NL * RC) * SC];   // [kg8][c][8kk] fp16, 655 KB
__device__ __half g_end1H[SC * SC];          // [jg8][c][8jj] fp16, 128 KB
__device__ float  g_xs0[8 * RC];

__device__ __forceinline__ void fma2(u64& d, u64 a, u64 b) {
    asm("fma.rn.f32x2 %0, %1, %2, %3;" : "=l"(d) : "l"(a), "l"(b), "l"(d));
}
__device__ __forceinline__ void add2(u64& d, u64 a, u64 b) {
    asm("add.rn.f32x2 %0, %1, %2;" : "=l"(d) : "l"(a), "l"(b));
}
__device__ __forceinline__ float2 upk(u64 v) {
    float2 r; asm("mov.b64 {%0, %1}, %2;" : "=f"(r.x), "=f"(r.y) : "l"(v));
    return r;
}
__device__ __forceinline__ float ex2(float v) {
    float r; asm("ex2.approx.f32 %0, %1;" : "=f"(r) : "f"(v));
    return r;
}
__device__ __forceinline__ unsigned h2u(__half2 h) {
    unsigned u; *reinterpret_cast<__half2*>(&u) = h; return u;
}
__device__ __forceinline__ __half2 u2h(unsigned u) {
    return *reinterpret_cast<__half2*>(&u);
}
__device__ __forceinline__ uint4 pack8h(float4 a, float4 c) {
    uint4 o;
    o.x = h2u(__floats2half2_rn(a.x, a.y));
    o.y = h2u(__floats2half2_rn(a.z, a.w));
    o.z = h2u(__floats2half2_rn(c.x, c.y));
    o.w = h2u(__floats2half2_rn(c.z, c.w));
    return o;
}
__device__ __forceinline__ float dot8h(uint4 s8, const float* u) {
    const float2 p0 = __half22float2(u2h(s8.x));
    const float2 p1 = __half22float2(u2h(s8.y));
    const float2 p2 = __half22float2(u2h(s8.z));
    const float2 p3 = __half22float2(u2h(s8.w));
    float a = fmaf(p0.x, u[0], 0.f);
    a = fmaf(p0.y, u[1], a);
    a = fmaf(p1.x, u[2], a);
    a = fmaf(p1.y, u[3], a);
    a = fmaf(p2.x, u[4], a);
    a = fmaf(p2.y, u[5], a);
    a = fmaf(p3.x, u[6], a);
    a = fmaf(p3.y, u[7], a);
    return a;
}

// ---------------------------------------------------------------- pack
// blocks 0..39: fold matmul; blocks 40+: fp16 skipT/end1T copies + start.
__global__ __launch_bounds__(256, 1)
void wn_pack(const float* __restrict__ x,
             const float* __restrict__ start_w,
             const float* __restrict__ filter_w,
             const float* __restrict__ gate_w,
             const float* __restrict__ res_w,
             const float* __restrict__ skip_w,
             const float* __restrict__ end1_w)
{
    const int blk = blockIdx.x;
    const int tid = threadIdx.x;

    if (blk < NL) {
        // ---- per-layer fold: slot L uses F/G of layer L, R of layer L-1
        const int L = blk;
        const float LOG2E = 1.4426950408889634f;
        __shared__ float Fk[RC][RC];   // -2*log2e * filter k0 taps
        __shared__ float Gk[RC][RC];   // -log2e   * gate   k0 taps
        __shared__ float Rp[RC][RC];   // R_{L-1} + I

        #pragma unroll
        for (int s = 0; s < 2; s++) {
            const int d  = tid + 256 * s;
            const int i  = d >> 4;
            const int rm = d & 15;
            const float4 fv = *(const float4*)(filter_w + L * 2048 + 4 * d);
            const float4 gv = *(const float4*)(gate_w   + L * 2048 + 4 * d);
            Fk[i][2 * rm]     = -2.f * LOG2E * fv.x;
            Fk[i][2 * rm + 1] = -2.f * LOG2E * fv.z;
            Gk[i][2 * rm]     = -LOG2E * gv.x;
            Gk[i][2 * rm + 1] = -LOG2E * gv.z;
        }
        if (L > 0) {
            const int k  = tid >> 3;
            const int j0 = (tid & 7) * 4;
            float4 r4 = *(const float4*)(res_w + (L - 1) * 1024 + k * RC + j0);
            if (k >= j0 && k < j0 + 4) (&r4.x)[k - j0] += 1.f;
            *(float4*)&Rp[k][j0] = r4;
        }
        __syncthreads();

        const int jg = tid >> 5;
        const int i  = tid & 31;
        float4 accA, accB;
        if (L == 0) {
            accA = *(const float4*)&Fk[i][4 * jg];
            accB = *(const float4*)&Gk[i][4 * jg];
        } else {
            accA = make_float4(0.f, 0.f, 0.f, 0.f);
            accB = make_float4(0.f, 0.f, 0.f, 0.f);
            #pragma unroll
            for (int k = 0; k < RC; k++) {
                const float4 r4 = *(const float4*)&Rp[k][4 * jg];
                const float fv = Fk[i][k];
                const float gv = Gk[i][k];
                accA.x = fmaf(fv, r4.x, accA.x); accA.y = fmaf(fv, r4.y, accA.y);
                accA.z = fmaf(fv, r4.z, accA.z); accA.w = fmaf(fv, r4.w, accA.w);
                accB.x = fmaf(gv, r4.x, accB.x); accB.y = fmaf(gv, r4.y, accB.y);
                accB.z = fmaf(gv, r4.z, accB.z); accB.w = fmaf(gv, r4.w, accB.w);
            }
        }
        ((float4*)g_pk)[L * LW + jg * 32 + i]       = accA;
        ((float4*)g_pk)[L * LW + 256 + jg * 32 + i] = accB;
    } else {
        // ---- copies: skipH (40960 u4), end1H (8192 u4), xs0 (256)
        const int NB = NL * RC * SC / 8;   // 40960
        const int NC = SC * SC / 8;        // 8192
        const int total = NB + NC + 8 * RC;
        const int nthr = 128 * 256;
        for (int idx = (blk - NL) * 256 + tid; idx < total; idx += nthr) {
            if (idx < NB) {
                const int kg8 = idx >> 8;
                const int c   = idx & 255;
                const int k0  = kg8 * 8;
                const int L   = k0 >> 5;
                const int j0  = k0 & 31;
                const float* src = skip_w + L * (SC * RC) + c * RC + j0;
                ((uint4*)g_skipH)[idx] =
                    pack8h(*(const float4*)src, *(const float4*)(src + 4));
            } else if (idx < NB + NC) {
                const int t   = idx - NB;
                const int jg8 = t >> 8;
                const int c   = t & 255;
                const float* src = end1_w + c * SC + jg8 * 8;
                ((uint4*)g_end1H)[t] =
                    pack8h(*(const float4*)src, *(const float4*)(src + 4));
            } else {
                const int t = idx - NB - NC;
                const int b = t / RC, i = t % RC;
                float s = 0.f;
                #pragma unroll
                for (int ci = 0; ci < CIN; ci++)
                    s += start_w[i * CIN + ci] * x[(b * CIN + ci) * T_IN + (T_IN - 1)];
                g_xs0[b * RC + i] = s;
            }
        }
    }
}

// ---------------------------------------------------------------- main
extern __shared__ float ring[];    // RING_BYTES dynamic smem

__global__ __launch_bounds__(288, 1)
void wn_main(const float* __restrict__ end1_b,
             const float* __restrict__ end2_w,
             const float* __restrict__ end2_b,
             float* __restrict__ out)
{
    const int b    = blockIdx.x;
    const int tid  = threadIdx.x;
    const int lane = tid & 31;
    const int warp = tid >> 5;

    __shared__ __align__(16) float us_all[NL * RC];   // 5.1 KB
    __shared__ __align__(16) float vbuf[2][RC];       // ping-pong state
    __shared__ __align__(16) float hs[SC];
    __shared__ float red8[8];

    // skip-thread channel: warps 1-8 -> c0 = tid-32 in [0,256), 1/thread.
    const int c0 = tid - 32;
    float acc0 = 0.f;

    // prologue: copy chunk 0 (256 threads x 16 float4, exact)
    if (tid < 256) {
        const float4* src = (const float4*)g_pk;
        float4*       dst = (float4*)ring;
        float4 t[16];
        #pragma unroll
        for (int k = 0; k < 16; k++) t[k] = src[tid + 256 * k];
        #pragma unroll
        for (int k = 0; k < 16; k++) dst[tid + 256 * k] = t[k];
    }
    if (warp == 0) vbuf[0][lane] = g_xs0[b * RC + lane];
    __syncthreads();

    for (int q = 0; q <= NCH; q++) {
        if (warp == 0) {
            if (q < NCH) {
                const float4* wc = (const float4*)ring + (q & 1) * CW;
                #pragma unroll
                for (int l = 0; l < CH; l++) {
                    const int L   = q * CH + l;
                    const int par = l & 1;          // CH even => par == L&1
                    const float4* wl = wc + l * LW + lane;

                    u64 fa = 0ull, fb = 0ull, ga = 0ull, gb = 0ull;
                    #pragma unroll
                    for (int jg = 0; jg < 8; jg++) {
                        const ulonglong2 vv = *(const ulonglong2*)&vbuf[par][4 * jg];
                        const ulonglong2 Aw = *(const ulonglong2*)(wl + jg * 32);
                        const ulonglong2 Bw = *(const ulonglong2*)(wl + 256 + jg * 32);
                        fma2(fa, Aw.x, vv.x); fma2(fb, Aw.y, vv.y);
                        fma2(ga, Bw.x, vv.x); fma2(gb, Bw.y, vv.y);
                    }
                    add2(fa, fa, fb);
                    add2(ga, ga, gb);
                    const float2 fp = upk(fa);
                    const float2 gp = upk(ga);
                    const float e1 = ex2(fp.x + fp.y);   // e^{-2f}
                    const float e2 = ex2(gp.x + gp.y);   // e^{-g}
                    // u = tanh(f)*sig(g) = (1-e1)/((1+e1)(1+e2))
                    const float u = __fdividef(1.f - e1, (1.f + e1) * (1.f + e2));
                    us_all[L * RC + lane] = u;
                    vbuf[par ^ 1][lane] = u;
                    __syncwarp();
                }
            }
        } else {
            // producers: batched stage of chunk q+1 (256 threads x 16 f4)
            if (q + 1 < NCH) {
                const float4* src = (const float4*)g_pk + (q + 1) * CW;
                float4*       dst = (float4*)ring + ((q + 1) & 1) * CW;
                float4 t[16];
                #pragma unroll
                for (int k = 0; k < 16; k++) t[k] = src[c0 + 256 * k];
                #pragma unroll
                for (int k = 0; k < 16; k++) dst[c0 + 256 * k] = t[k];
            }
            // fp16 skip GEMM for chunk q-1: 32 k-groups of 8, one channel
            if (q >= 1) {
                const int cq = q - 1;
                const uint4* sp = (const uint4*)g_skipH + (32 * cq) * 256 + c0;
                const float* up = us_all + cq * (CH * RC);
                #pragma unroll
                for (int kg8 = 0; kg8 < 32; kg8++)
                    acc0 += dot8h(sp[kg8 * 256], up + 8 * kg8);
            }
        }
        __syncthreads();
    }

    // ---- head (fp16 end1), one channel per skip thread
    if (warp > 0) hs[c0] = fmaxf(acc0, 0.f);
    __syncthreads();

    float o = 0.f;
    if (warp > 0) {
        float e0 = end1_b[c0];
        const uint4* ep = (const uint4*)g_end1H + c0;
        #pragma unroll
        for (int jg8 = 0; jg8 < 32; jg8++)
            e0 += dot8h(ep[jg8 * 256], hs + 8 * jg8);
        o = end2_w[c0] * fmaxf(e0, 0.f);
    }
    #pragma unroll
    for (int off = 16; off > 0; off >>= 1)
        o += __shfl_xor_sync(FULLM, o, off);
    if (warp > 0 && lane == 0) red8[warp - 1] = o;
    __syncthreads();
    if (tid == 0) {
        float tot = 0.f;
        #pragma unroll
        for (int w = 0; w < 8; w++) tot += red8[w];
        out[b] = tot + end2_b[0];
    }
}

extern "C" void kernel_launch(void* const* d_in, const int* in_sizes, int n_in,
                              void* d_out, int out_size)
{
    const float* x        = (const float*)d_in[0];
    const float* start_w  = (const float*)d_in[1];
    const float* filter_w = (const float*)d_in[2];
    const float* gate_w   = (const float*)d_in[3];
    const float* res_w    = (const float*)d_in[4];
    const float* skip_w   = (const float*)d_in[5];
    const float* end1_w   = (const float*)d_in[6];
    const float* end1_b   = (const float*)d_in[7];
    const float* end2_w   = (const float*)d_in[8];
    const float* end2_b   = (const float*)d_in[9];
    float* out = (float*)d_out;

    cudaFuncSetAttribute(wn_main,
                         cudaFuncAttributeMaxDynamicSharedMemorySize,
                         RING_BYTES);

    wn_pack<<<168, 256>>>(x, start_w, filter_w, gate_w, res_w, skip_w, end1_w);
    wn_main<<<8, 288, RING_BYTES>>>(end1_b, end2_w, end2_b, out);
}